// round 9
// baseline (speedup 1.0000x reference)
#include <cuda_runtime.h>
#include <cuda_bf16.h>
#include <cstdint>

#define BATCH 4
#define CIN   128
#define COUT  256
#define HW    1024
#define TILE_O 64
#define TILE_P 64
#define THREADS 256

// smem strides: 16B multiples with (stride/4 mod 32)==4 -> ldmatrix rows walk
// 4 banks per row, conflict-free per 8-row phase.
#define A_STRIDE 272                       // 128 halves + 8 pad
#define B_STRIDE 144                       // 64 halves + 8 pad
#define SMEM_AP  0
#define SMEM_AM  (TILE_O * A_STRIDE)       // 17408
#define SMEM_B0  (2 * TILE_O * A_STRIDE)   // 34816
#define SMEM_B1  (SMEM_B0 + CIN * B_STRIDE)        // 53248
#define SMEM_TOTAL (SMEM_B1 + CIN * B_STRIDE)      // 71680

__device__ __forceinline__ uint32_t smem_u32(const void* p) {
    uint32_t a;
    asm("{ .reg .u64 t; cvta.to.shared.u64 t, %1; cvt.u32.u64 %0, t; }" : "=r"(a) : "l"(p));
    return a;
}
__device__ __forceinline__ uint32_t pack_bf16x2(float lo, float hi) {
    uint32_t r;
    asm("cvt.rn.bf16x2.f32 %0, %1, %2;" : "=r"(r) : "f"(hi), "f"(lo));
    return r;
}
__device__ __forceinline__ uint32_t relu2(uint32_t v) {          // max.bf16x2(v, +0)
    uint32_t r;
    asm("max.bf16x2 %0, %1, %2;" : "=r"(r) : "r"(v), "r"(0u));
    return r;
}
__device__ __forceinline__ void sts64(uint32_t addr, uint32_t a, uint32_t b) {
    asm volatile("st.shared.v2.b32 [%0], {%1,%2};" :: "r"(addr), "r"(a), "r"(b) : "memory");
}
__device__ __forceinline__ void ldsm_x4(uint32_t addr, uint32_t* r) {
    asm volatile("ldmatrix.sync.aligned.m8n8.x4.shared.b16 {%0,%1,%2,%3}, [%4];"
                 : "=r"(r[0]), "=r"(r[1]), "=r"(r[2]), "=r"(r[3]) : "r"(addr));
}
__device__ __forceinline__ void ldsm_x4_trans(uint32_t addr, uint32_t* r) {
    asm volatile("ldmatrix.sync.aligned.m8n8.x4.trans.shared.b16 {%0,%1,%2,%3}, [%4];"
                 : "=r"(r[0]), "=r"(r[1]), "=r"(r[2]), "=r"(r[3]) : "r"(addr));
}
__device__ __forceinline__ void mma_16816(float* c, const uint32_t* a, const uint32_t* b) {
    asm volatile(
        "mma.sync.aligned.m16n8k16.row.col.f32.bf16.bf16.f32 "
        "{%0,%1,%2,%3}, {%4,%5,%6,%7}, {%8,%9}, {%0,%1,%2,%3};"
        : "+f"(c[0]), "+f"(c[1]), "+f"(c[2]), "+f"(c[3])
        : "r"(a[0]), "r"(a[1]), "r"(a[2]), "r"(a[3]), "r"(b[0]), "r"(b[1]));
}

// One 64x64 tile: mainloop over K=128 with register-side sign split + epilogue.
__device__ __forceinline__ void compute_tile(uint32_t aAddrP, uint32_t aAddrM,
                                             uint32_t bBase, float* ob) {
    float acc[4][4];
#pragma unroll
    for (int ns = 0; ns < 4; ns++)
#pragma unroll
        for (int j = 0; j < 4; j++) acc[ns][j] = 0.f;

#pragma unroll
    for (int kk = 0; kk < CIN / 16; kk++) {
        uint32_t ap[4], am[4];
        ldsm_x4(aAddrP + kk * 32, ap);
        ldsm_x4(aAddrM + kk * 32, am);
        uint32_t bx[2][4];
        ldsm_x4_trans(bBase + (uint32_t)kk * (16 * B_STRIDE), bx[0]);
        ldsm_x4_trans(bBase + (uint32_t)kk * (16 * B_STRIDE) + 32, bx[1]);
        uint32_t xp[2][4], xm[2][4];
#pragma unroll
        for (int g = 0; g < 2; g++)
#pragma unroll
            for (int j = 0; j < 4; j++) {
                xp[g][j] = relu2(bx[g][j]);
                xm[g][j] = relu2(bx[g][j] ^ 0x80008000u);
            }
        mma_16816(acc[0], ap, &xp[0][0]);
        mma_16816(acc[1], ap, &xp[0][2]);
        mma_16816(acc[2], ap, &xp[1][0]);
        mma_16816(acc[3], ap, &xp[1][2]);
        mma_16816(acc[0], am, &xm[0][0]);
        mma_16816(acc[1], am, &xm[0][2]);
        mma_16816(acc[2], am, &xm[1][0]);
        mma_16816(acc[3], am, &xm[1][2]);
    }
#pragma unroll
    for (int ns = 0; ns < 4; ns++) {
        *(float2*)(ob + ns * 8)                  = make_float2(acc[ns][0], acc[ns][1]);
        *(float2*)(ob + (size_t)8 * HW + ns * 8) = make_float2(acc[ns][2], acc[ns][3]);
    }
}

__global__ __launch_bounds__(THREADS, 2)
void pw_relu_mma_kernel(const float* __restrict__ x,
                        const float* __restrict__ w,
                        float* __restrict__ out) {
    extern __shared__ char smem[];
    const uint32_t sb = smem_u32(smem);
    const int tid  = threadIdx.x;
    const int lane = tid & 31;
    const int wid  = tid >> 5;
    const int b  = blockIdx.z;
    const int o0 = blockIdx.y * TILE_O;
    const int p0 = blockIdx.x * (2 * TILE_P);   // this CTA covers p0 and p0+64

    // ---- staging maps ----
    const int pf = tid & 15;               // p = 4*pf within a 64-wide tile
    const int i0 = tid >> 4;               // 0..15 (X row base)
    const float* xb = x + (size_t)b * CIN * HW + p0 + pf * 4;
    const int iv = tid & 31;               // i = 4*iv
    const int oo = tid >> 5;               // 0..7  (W row base)
    const float* wb = w + (size_t)(o0 + oo) * CIN + iv * 4;

    // ---- front-load W + X(tile0) ----
    float4 wv[8], xv[8];
#pragma unroll
    for (int it = 0; it < 8; it++)
        wv[it] = *(const float4*)(wb + (size_t)(it * 8) * CIN);      // rows o = oo+8it
#pragma unroll
    for (int it = 0; it < 8; it++)
        xv[it] = *(const float4*)(xb + (size_t)(i0 + it * 16) * HW);

    // ---- stage W as A+/A- (staged once, reused for both tiles) ----
#pragma unroll
    for (int it = 0; it < 8; it++) {
        const int o = oo + it * 8;
        float4 v = wv[it];
        uint32_t pr0 = pack_bf16x2(fmaxf(v.x, 0.f), fmaxf(v.y, 0.f));
        uint32_t pr1 = pack_bf16x2(fmaxf(v.z, 0.f), fmaxf(v.w, 0.f));
        uint32_t mr0 = pack_bf16x2(fmaxf(-v.x, 0.f), fmaxf(-v.y, 0.f));
        uint32_t mr1 = pack_bf16x2(fmaxf(-v.z, 0.f), fmaxf(-v.w, 0.f));
        sts64(sb + SMEM_AP + (uint32_t)o * A_STRIDE + iv * 8, pr0, pr1);
        sts64(sb + SMEM_AM + (uint32_t)o * A_STRIDE + iv * 8, mr0, mr1);
    }
    // ---- stage X tile0 (plain bf16; sign split happens in registers) ----
#pragma unroll
    for (int it = 0; it < 8; it++) {
        const int i = i0 + it * 16;
        float4 v = xv[it];
        sts64(sb + SMEM_B0 + (uint32_t)i * B_STRIDE + pf * 8,
              pack_bf16x2(v.x, v.y), pack_bf16x2(v.z, v.w));
    }
    __syncthreads();

    // ---- issue X(tile1) loads NOW: latency hidden under compute of tile0 ----
    float4 yv[8];
#pragma unroll
    for (int it = 0; it < 8; it++)
        yv[it] = *(const float4*)(xb + 64 + (size_t)(i0 + it * 16) * HW);

    // ---- per-warp fragment bases ----
    const int warp_m = wid & 3;    // 4 -> 64 o
    const int warp_n = wid >> 2;   // 2 -> 64 p
    const uint32_t aAddrP = sb + SMEM_AP + (uint32_t)(warp_m * 16 + (lane & 15)) * A_STRIDE
                            + (uint32_t)(lane >> 4) * 16;
    const uint32_t aAddrM = aAddrP + (SMEM_AM - SMEM_AP);
    const uint32_t bFrag  = (uint32_t)(lane & 15) * B_STRIDE
                            + (uint32_t)(warp_n * 64) + (uint32_t)(lane >> 4) * 16;
    const int r  = lane >> 2;
    const int c2 = (lane & 3) * 2;
    float* ob0 = out + ((size_t)b * COUT + o0 + warp_m * 16 + r) * HW
                 + p0 + warp_n * 32 + c2;

    // ---- tile0: compute + store (X1 LDGs in flight underneath) ----
    compute_tile(aAddrP, aAddrM, sb + SMEM_B0 + bFrag, ob0);

    // ---- stage X tile1 into the second buffer ----
#pragma unroll
    for (int it = 0; it < 8; it++) {
        const int i = i0 + it * 16;
        float4 v = yv[it];
        sts64(sb + SMEM_B1 + (uint32_t)i * B_STRIDE + pf * 8,
              pack_bf16x2(v.x, v.y), pack_bf16x2(v.z, v.w));
    }
    __syncthreads();

    // ---- tile1: compute + store ----
    compute_tile(aAddrP, aAddrM, sb + SMEM_B1 + bFrag, ob0 + 64);
}

extern "C" void kernel_launch(void* const* d_in, const int* in_sizes, int n_in,
                              void* d_out, int out_size) {
    const float* x = (const float*)d_in[0];   // (4,128,32,32)
    const float* w = (const float*)d_in[1];   // (256*128,1,1,1)
    float* out = (float*)d_out;               // (4,256,32,32)
    static bool attr_set = false;
    if (!attr_set) {
        cudaFuncSetAttribute(pw_relu_mma_kernel,
                             cudaFuncAttributeMaxDynamicSharedMemorySize, SMEM_TOTAL);
        attr_set = true;
    }
    dim3 grid(HW / (2 * TILE_P), COUT / TILE_O, BATCH);   // (8, 4, 4) = 128 CTAs
    pw_relu_mma_kernel<<<grid, THREADS, SMEM_TOTAL>>>(x, w, out);
}